// round 2
// baseline (speedup 1.0000x reference)
#include <cuda_runtime.h>
#include <cuda_bf16.h>
#include <math.h>
#include <stdint.h>

#define NTOK 4096
#define D 1024
#define H 4096
#define NE 8

__device__ double d_wsum[17];
__device__ float  d_wscale[17];
__device__ __nv_bfloat16 d_gwq[NE * D];
__device__ __nv_bfloat16 d_w1q[(size_t)NE * H * D];
__device__ __nv_bfloat16 d_w2q[(size_t)NE * D * H];
__device__ __nv_bfloat16 d_qx[(size_t)NTOK * D];
__device__ float d_sx[NTOK];
__device__ float d_gates[NTOK * NE];
__device__ float d_abuf[(size_t)NTOK * NE * H];
__device__ __nv_bfloat16 d_qa[(size_t)NTOK * NE * H];
__device__ float d_sa[NTOK * NE];

__device__ __forceinline__ float gelu_exact(float h) {
    return 0.5f * h * (1.0f + erff(h * 0.70710678118654752440f));
}
__device__ __forceinline__ void mma16816(float* d, const uint32_t* a, const uint32_t* b) {
    asm volatile(
        "mma.sync.aligned.m16n8k16.row.col.f32.bf16.bf16.f32 "
        "{%0,%1,%2,%3}, {%4,%5,%6,%7}, {%8,%9}, {%0,%1,%2,%3};\n"
        : "+f"(d[0]), "+f"(d[1]), "+f"(d[2]), "+f"(d[3])
        : "r"(a[0]), "r"(a[1]), "r"(a[2]), "r"(a[3]), "r"(b[0]), "r"(b[1]));
}

__global__ void k_init() { if (threadIdx.x < 17) d_wsum[threadIdx.x] = 0.0; }

// sum |w|, 4096 elements per block, double accumulation
__global__ void __launch_bounds__(256) k_abs_sum(const float* __restrict__ w, int slot0) {
    __shared__ double sd[256];
    size_t base = ((size_t)blockIdx.y * gridDim.x + blockIdx.x) * 4096;
    float s = 0.f;
    for (int i = threadIdx.x; i < 4096; i += 256) s += fabsf(w[base + i]);
    sd[threadIdx.x] = (double)s;
    __syncthreads();
    for (int o = 128; o; o >>= 1) {
        if (threadIdx.x < o) sd[threadIdx.x] += sd[threadIdx.x + o];
        __syncthreads();
    }
    if (threadIdx.x == 0) atomicAdd(&d_wsum[slot0 + blockIdx.y], sd[0]);
}

__global__ void k_finalize() {
    int i = threadIdx.x;
    if (i < 17) {
        double cnt = (i == 0) ? (double)(NE * D) : (double)H * (double)D;
        d_wscale[i] = 1.0f / fmaxf((float)(d_wsum[i] / cnt), 1e-5f);
    }
}

// ternarize -> bf16 {-1,0,1}
__global__ void __launch_bounds__(256) k_quant_w(const float* __restrict__ w, int which,
                                                 int slot0, size_t n_per) {
    __nv_bfloat16* q = (which == 0) ? d_gwq : (which == 1) ? d_w1q : d_w2q;
    int e = blockIdx.y;
    float s = d_wscale[slot0 + e];
    size_t base = (size_t)e * n_per;
    for (size_t i = (size_t)blockIdx.x * 256 + threadIdx.x; i < n_per;
         i += (size_t)gridDim.x * 256) {
        float v = fminf(fmaxf(rintf(w[base + i] * s), -1.f), 1.f);
        q[base + i] = __float2bfloat16(v);
    }
}

// per-token rmsnorm + act quant + gate softmax
__global__ void __launch_bounds__(256) k_xquant(const float* __restrict__ x,
                                                const float* __restrict__ gb) {
    const int t = blockIdx.x;
    const float* xr = x + (size_t)t * D;
    __shared__ float sq[D];
    __shared__ float wred[16], red2[2], slog[NE];
    const int tid = threadIdx.x;
    float v[4];
    float ss = 0.f, am = 0.f;
#pragma unroll
    for (int i = 0; i < 4; i++) {
        v[i] = xr[tid + i * 256];
        ss += v[i] * v[i];
        am = fmaxf(am, fabsf(v[i]));
    }
    for (int o = 16; o; o >>= 1) {
        ss += __shfl_xor_sync(0xffffffffu, ss, o);
        am = fmaxf(am, __shfl_xor_sync(0xffffffffu, am, o));
    }
    if ((tid & 31) == 0) { wred[tid >> 5] = ss; wred[8 + (tid >> 5)] = am; }
    __syncthreads();
    if (tid == 0) {
        float S = 0.f, A = 0.f;
        for (int i = 0; i < 8; i++) { S += wred[i]; A = fmaxf(A, wred[8 + i]); }
        red2[0] = S; red2[1] = A;
    }
    __syncthreads();
    float nrm = fmaxf(sqrtf(red2[0]), 1e-12f);
    float scale = 127.0f / fmaxf(red2[1] / nrm * 32.0f, 1e-5f);
#pragma unroll
    for (int i = 0; i < 4; i++) {
        float q = fminf(fmaxf(rintf((v[i] / nrm * 32.0f) * scale), -128.f), 127.f);
        sq[tid + i * 256] = q;
        d_qx[(size_t)t * D + tid + i * 256] = __float2bfloat16(q);
    }
    if (tid == 0) d_sx[t] = scale;
    __syncthreads();
    const int w = tid >> 5, l = tid & 31;
    float acc = 0.f;
    for (int i = l; i < D; i += 32) acc += sq[i] * __bfloat162float(d_gwq[w * D + i]);
    for (int o = 16; o; o >>= 1) acc += __shfl_xor_sync(0xffffffffu, acc, o);
    if (l == 0) slog[w] = acc;
    __syncthreads();
    if (tid == 0) {
        float inv = 1.0f / (scale * d_wscale[0]);
        float lg[NE], mx = -1e30f;
        for (int e = 0; e < NE; e++) { lg[e] = slog[e] * inv + gb[e]; mx = fmaxf(mx, lg[e]); }
        float se = 0.f;
        for (int e = 0; e < NE; e++) { lg[e] = expf(lg[e] - mx); se += lg[e]; }
        for (int e = 0; e < NE; e++) d_gates[t * NE + e] = lg[e] / se;
    }
}

// GEMM1: qx[4096,1024] @ w1q[e][4096,1024]^T, 128x128x32 tiles, gelu epilogue
__global__ void __launch_bounds__(256) k_gemm1(const float* __restrict__ b1) {
    __shared__ __align__(16) __nv_bfloat16 As[2][128 * 40];
    __shared__ __align__(16) __nv_bfloat16 Bs[2][128 * 40];
    const int e = blockIdx.z;
    const __nv_bfloat16* Ag = d_qx + (size_t)blockIdx.x * 128 * D;
    const __nv_bfloat16* Bg = d_w1q + ((size_t)e * H + (size_t)blockIdx.y * 128) * D;
    const int tid = threadIdx.x;
    const int warp = tid >> 5, lane = tid & 31;
    const int wm = warp >> 1, wn = warp & 1;
    const int g = lane >> 2, tq = lane & 3;
    const int lr = tid >> 2, lc = (tid & 3) * 8;

    float c[2][8][4];
#pragma unroll
    for (int i = 0; i < 2; i++)
#pragma unroll
        for (int j = 0; j < 8; j++)
#pragma unroll
            for (int k = 0; k < 4; k++) c[i][j][k] = 0.f;

    float4 ar0, ar1, br0, br1;
    ar0 = *(const float4*)(Ag + (size_t)lr * D + lc);
    ar1 = *(const float4*)(Ag + (size_t)(lr + 64) * D + lc);
    br0 = *(const float4*)(Bg + (size_t)lr * D + lc);
    br1 = *(const float4*)(Bg + (size_t)(lr + 64) * D + lc);
    *(float4*)(&As[0][lr * 40 + lc]) = ar0;
    *(float4*)(&As[0][(lr + 64) * 40 + lc]) = ar1;
    *(float4*)(&Bs[0][lr * 40 + lc]) = br0;
    *(float4*)(&Bs[0][(lr + 64) * 40 + lc]) = br1;
    __syncthreads();

    const int KT = D / 32;
    for (int kt = 0; kt < KT; kt++) {
        const int cur = kt & 1;
        if (kt + 1 < KT) {
            const int k0 = (kt + 1) * 32;
            ar0 = *(const float4*)(Ag + (size_t)lr * D + k0 + lc);
            ar1 = *(const float4*)(Ag + (size_t)(lr + 64) * D + k0 + lc);
            br0 = *(const float4*)(Bg + (size_t)lr * D + k0 + lc);
            br1 = *(const float4*)(Bg + (size_t)(lr + 64) * D + k0 + lc);
        }
#pragma unroll
        for (int ks = 0; ks < 2; ks++) {
            const int kk = ks * 16;
            uint32_t af[2][4], bf[8][2];
#pragma unroll
            for (int mf = 0; mf < 2; mf++) {
                const int rb = wm * 32 + mf * 16;
                af[mf][0] = *(const uint32_t*)(&As[cur][(rb + g) * 40 + kk + tq * 2]);
                af[mf][1] = *(const uint32_t*)(&As[cur][(rb + g + 8) * 40 + kk + tq * 2]);
                af[mf][2] = *(const uint32_t*)(&As[cur][(rb + g) * 40 + kk + 8 + tq * 2]);
                af[mf][3] = *(const uint32_t*)(&As[cur][(rb + g + 8) * 40 + kk + 8 + tq * 2]);
            }
#pragma unroll
            for (int nf = 0; nf < 8; nf++) {
                const int cb = wn * 64 + nf * 8;
                bf[nf][0] = *(const uint32_t*)(&Bs[cur][(cb + g) * 40 + kk + tq * 2]);
                bf[nf][1] = *(const uint32_t*)(&Bs[cur][(cb + g) * 40 + kk + 8 + tq * 2]);
            }
#pragma unroll
            for (int mf = 0; mf < 2; mf++)
#pragma unroll
                for (int nf = 0; nf < 8; nf++) mma16816(c[mf][nf], af[mf], bf[nf]);
        }
        if (kt + 1 < KT) {
            const int nb = (kt + 1) & 1;
            *(float4*)(&As[nb][lr * 40 + lc]) = ar0;
            *(float4*)(&As[nb][(lr + 64) * 40 + lc]) = ar1;
            *(float4*)(&Bs[nb][lr * 40 + lc]) = br0;
            *(float4*)(&Bs[nb][(lr + 64) * 40 + lc]) = br1;
        }
        __syncthreads();
    }

    const float sw1 = d_wscale[1 + e];
#pragma unroll
    for (int mf = 0; mf < 2; mf++) {
        const int row0 = blockIdx.x * 128 + wm * 32 + mf * 16 + g;
        const float r0 = 1.0f / (d_sx[row0] * sw1);
        const float r1 = 1.0f / (d_sx[row0 + 8] * sw1);
#pragma unroll
        for (int nf = 0; nf < 8; nf++) {
            const int col = blockIdx.y * 128 + wn * 64 + nf * 8 + tq * 2;
            const float bb0 = b1[e * H + col];
            const float bb1 = b1[e * H + col + 1];
            float2 o0, o1;
            o0.x = gelu_exact(c[mf][nf][0] * r0 + bb0);
            o0.y = gelu_exact(c[mf][nf][1] * r0 + bb1);
            o1.x = gelu_exact(c[mf][nf][2] * r1 + bb0);
            o1.y = gelu_exact(c[mf][nf][3] * r1 + bb1);
            *(float2*)(&d_abuf[((size_t)row0 * NE + e) * H + col]) = o0;
            *(float2*)(&d_abuf[((size_t)(row0 + 8) * NE + e) * H + col]) = o1;
        }
    }
}

// per-(token,expert) rmsnorm + quant of gelu activations
__global__ void __launch_bounds__(256) k_aquant() {
    const size_t r = blockIdx.x;  // t*NE+e
    const float4* a = (const float4*)(d_abuf + r * (size_t)H);
    __shared__ float wss[8], wam[8], red2[2];
    const int tid = threadIdx.x;
    float4 v[4];
    float ss = 0.f, am = 0.f;
#pragma unroll
    for (int i = 0; i < 4; i++) {
        v[i] = a[tid + i * 256];
        ss += v[i].x * v[i].x + v[i].y * v[i].y + v[i].z * v[i].z + v[i].w * v[i].w;
        am = fmaxf(am, fmaxf(fmaxf(fabsf(v[i].x), fabsf(v[i].y)),
                             fmaxf(fabsf(v[i].z), fabsf(v[i].w))));
    }
    for (int o = 16; o; o >>= 1) {
        ss += __shfl_xor_sync(0xffffffffu, ss, o);
        am = fmaxf(am, __shfl_xor_sync(0xffffffffu, am, o));
    }
    if ((tid & 31) == 0) { wss[tid >> 5] = ss; wam[tid >> 5] = am; }
    __syncthreads();
    if (tid == 0) {
        float S = 0.f, A = 0.f;
        for (int i = 0; i < 8; i++) { S += wss[i]; A = fmaxf(A, wam[i]); }
        red2[0] = S; red2[1] = A;
    }
    __syncthreads();
    const float nrm = fmaxf(sqrtf(red2[0]), 1e-12f);
    const float scale = 127.0f / fmaxf(red2[1] / nrm * 64.0f, 1e-5f);
    if (tid == 0) d_sa[r] = scale;
    __nv_bfloat16* qo = d_qa + r * (size_t)H;
#pragma unroll
    for (int i = 0; i < 4; i++) {
        float q0 = fminf(fmaxf(rintf((v[i].x / nrm * 64.0f) * scale), -128.f), 127.f);
        float q1 = fminf(fmaxf(rintf((v[i].y / nrm * 64.0f) * scale), -128.f), 127.f);
        float q2 = fminf(fmaxf(rintf((v[i].z / nrm * 64.0f) * scale), -128.f), 127.f);
        float q3 = fminf(fmaxf(rintf((v[i].w / nrm * 64.0f) * scale), -128.f), 127.f);
        uint2 u;
        u.x = (uint32_t)__bfloat16_as_ushort(__float2bfloat16(q0)) |
              ((uint32_t)__bfloat16_as_ushort(__float2bfloat16(q1)) << 16);
        u.y = (uint32_t)__bfloat16_as_ushort(__float2bfloat16(q2)) |
              ((uint32_t)__bfloat16_as_ushort(__float2bfloat16(q3)) << 16);
        *(uint2*)(qo + (tid + i * 256) * 4) = u;
    }
}

// GEMM2: per expert qa @ w2q^T, 64x128 tiles, gate-weighted accumulation
__global__ void __launch_bounds__(256) k_gemm2(const float* __restrict__ b2,
                                               float* __restrict__ out) {
    __shared__ __align__(16) __nv_bfloat16 As[2][64 * 40];
    __shared__ __align__(16) __nv_bfloat16 Bs[2][128 * 40];
    const int tid = threadIdx.x;
    const int warp = tid >> 5, lane = tid & 31;
    const int wm = warp >> 2, wn = warp & 3;
    const int g = lane >> 2, tq = lane & 3;
    const int lr = tid >> 2, lc = (tid & 3) * 8;

    float fin[2][4][4];
#pragma unroll
    for (int i = 0; i < 2; i++)
#pragma unroll
        for (int j = 0; j < 4; j++)
#pragma unroll
            for (int k = 0; k < 4; k++) fin[i][j][k] = 0.f;

    for (int e = 0; e < NE; e++) {
        const __nv_bfloat16* Ag = d_qa + ((size_t)blockIdx.x * 64 * NE + e) * H;
        const __nv_bfloat16* Bg = d_w2q + ((size_t)e * D + (size_t)blockIdx.y * 128) * H;
        float c[2][4][4];
#pragma unroll
        for (int i = 0; i < 2; i++)
#pragma unroll
            for (int j = 0; j < 4; j++)
#pragma unroll
                for (int k = 0; k < 4; k++) c[i][j][k] = 0.f;

        float4 ar, br0, br1;
        ar = *(const float4*)(Ag + (size_t)lr * NE * H + lc);
        br0 = *(const float4*)(Bg + (size_t)lr * H + lc);
        br1 = *(const float4*)(Bg + (size_t)(lr + 64) * H + lc);
        *(float4*)(&As[0][lr * 40 + lc]) = ar;
        *(float4*)(&Bs[0][lr * 40 + lc]) = br0;
        *(float4*)(&Bs[0][(lr + 64) * 40 + lc]) = br1;
        __syncthreads();

        const int KT = H / 32;
        for (int kt = 0; kt < KT; kt++) {
            const int cur = kt & 1;
            if (kt + 1 < KT) {
                const int k0 = (kt + 1) * 32;
                ar = *(const float4*)(Ag + (size_t)lr * NE * H + k0 + lc);
                br0 = *(const float4*)(Bg + (size_t)lr * H + k0 + lc);
                br1 = *(const float4*)(Bg + (size_t)(lr + 64) * H + k0 + lc);
            }
#pragma unroll
            for (int ks = 0; ks < 2; ks++) {
                const int kk = ks * 16;
                uint32_t af[2][4], bf[4][2];
#pragma unroll
                for (int mf = 0; mf < 2; mf++) {
                    const int rb = wm * 32 + mf * 16;
                    af[mf][0] = *(const uint32_t*)(&As[cur][(rb + g) * 40 + kk + tq * 2]);
                    af[mf][1] = *(const uint32_t*)(&As[cur][(rb + g + 8) * 40 + kk + tq * 2]);
                    af[mf][2] = *(const uint32_t*)(&As[cur][(rb + g) * 40 + kk + 8 + tq * 2]);
                    af[mf][3] = *(const uint32_t*)(&As[cur][(rb + g + 8) * 40 + kk + 8 + tq * 2]);
                }
#pragma unroll
                for (int nf = 0; nf < 4; nf++) {
                    const int cb = wn * 32 + nf * 8;
                    bf[nf][0] = *(const uint32_t*)(&Bs[cur][(cb + g) * 40 + kk + tq * 2]);
                    bf[nf][1] = *(const uint32_t*)(&Bs[cur][(cb + g) * 40 + kk + 8 + tq * 2]);
                }
#pragma unroll
                for (int mf = 0; mf < 2; mf++)
#pragma unroll
                    for (int nf = 0; nf < 4; nf++) mma16816(c[mf][nf], af[mf], bf[nf]);
            }
            if (kt + 1 < KT) {
                const int nb = (kt + 1) & 1;
                *(float4*)(&As[nb][lr * 40 + lc]) = ar;
                *(float4*)(&Bs[nb][lr * 40 + lc]) = br0;
                *(float4*)(&Bs[nb][(lr + 64) * 40 + lc]) = br1;
            }
            __syncthreads();
        }

        const float sw2 = d_wscale[9 + e];
#pragma unroll
        for (int mf = 0; mf < 2; mf++) {
            const int r0 = blockIdx.x * 64 + wm * 32 + mf * 16 + g;
            const float g0 = d_gates[r0 * NE + e];
            const float g1 = d_gates[(r0 + 8) * NE + e];
            const float i0 = 1.0f / (d_sa[r0 * NE + e] * sw2);
            const float i1 = 1.0f / (d_sa[(r0 + 8) * NE + e] * sw2);
#pragma unroll
            for (int nf = 0; nf < 4; nf++) {
                const int col = blockIdx.y * 128 + wn * 32 + nf * 8 + tq * 2;
                const float bb0 = b2[e * D + col];
                const float bb1 = b2[e * D + col + 1];
                fin[mf][nf][0] += g0 * (c[mf][nf][0] * i0 + bb0);
                fin[mf][nf][1] += g0 * (c[mf][nf][1] * i0 + bb1);
                fin[mf][nf][2] += g1 * (c[mf][nf][2] * i1 + bb0);
                fin[mf][nf][3] += g1 * (c[mf][nf][3] * i1 + bb1);
            }
        }
        __syncthreads();
    }

#pragma unroll
    for (int mf = 0; mf < 2; mf++) {
        const int r0 = blockIdx.x * 64 + wm * 32 + mf * 16 + g;
#pragma unroll
        for (int nf = 0; nf < 4; nf++) {
            const int col = blockIdx.y * 128 + wn * 32 + nf * 8 + tq * 2;
            *(float2*)(&out[(size_t)r0 * D + col]) = make_float2(fin[mf][nf][0], fin[mf][nf][1]);
            *(float2*)(&out[(size_t)(r0 + 8) * D + col]) = make_float2(fin[mf][nf][2], fin[mf][nf][3]);
        }
    }
}

extern "C" void kernel_launch(void* const* d_in, const int* in_sizes, int n_in,
                              void* d_out, int out_size) {
    const float* x  = (const float*)d_in[0];
    const float* gw = (const float*)d_in[1];
    const float* gb = (const float*)d_in[2];
    const float* w1 = (const float*)d_in[3];
    const float* b1 = (const float*)d_in[4];
    const float* w2 = (const float*)d_in[5];
    const float* b2 = (const float*)d_in[6];
    float* out = (float*)d_out;

    k_init<<<1, 32>>>();
    k_abs_sum<<<dim3(2, 1), 256>>>(gw, 0);
    k_abs_sum<<<dim3((H * D) / 4096, NE), 256>>>(w1, 1);
    k_abs_sum<<<dim3((H * D) / 4096, NE), 256>>>(w2, 9);
    k_finalize<<<1, 32>>>();
    k_quant_w<<<dim3(8, 1), 256>>>(gw, 0, 0, (size_t)NE * D);
    k_quant_w<<<dim3(256, NE), 256>>>(w1, 1, 1, (size_t)H * D);
    k_quant_w<<<dim3(256, NE), 256>>>(w2, 2, 9, (size_t)H * D);
    k_xquant<<<NTOK, 256>>>(x, gb);
    k_gemm1<<<dim3(NTOK / 128, H / 128, NE), 256>>>(b1);
    k_aquant<<<NTOK * NE, 256>>>();
    k_gemm2<<<dim3(NTOK / 64, D / 128), 256>>>(b2, out);
}